// round 13
// baseline (speedup 1.0000x reference)
#include <cuda_runtime.h>
#include <cuda_bf16.h>
#include <stdint.h>

// PointPillars BEV scatter as a full-output gather.
//   out(B, C, H, W): out[b,c,y,x] = feat[map[b,y,x], c]  (or 0 if empty)
//
// R9 (resubmit): branch-free clamp+select loads (like best R6) but TWO
// independent cell-quads per thread, all loads issued up front for MLP=10.
// Map cleared via cudaMemsetAsync node (0xFF == -1).

#define BEV_H 496
#define BEV_W 432
#define C_CH  64
#define HW    (BEV_H * BEV_W)     // 214,272
#define HW8   (HW / 8)            // 26,784  (W % 8 == 0)
#define MAXB  8

__device__ int g_pillar_map[MAXB * HW];

// ---------------------------------------------------------------------------
// Kernel 1: scatter pillar indices (collision-free coords by construction)
// ---------------------------------------------------------------------------
__global__ void scatter_map_kernel(const int* __restrict__ coords, int M) {
    int m = blockIdx.x * blockDim.x + threadIdx.x;
    if (m < M) {
        int b = coords[3 * m + 0];
        int y = coords[3 * m + 1];
        int x = coords[3 * m + 2];
        g_pillar_map[b * HW + y * BEV_W + x] = m;
    }
}

// ---------------------------------------------------------------------------
// Kernel 2: gather. Thread i -> (b, c4, r8), r8 = cell OCTET (8 cells).
// 2 map int4 loads + 8 clamped LDG.128 feat loads (all independent, issued
// before any consumer) + selects + 2 register 4x4 transposes + 8 STG.128
// streaming stores into 4 channel planes. 32 outputs/thread, branch-free.
// ---------------------------------------------------------------------------
__global__ void __launch_bounds__(256) gather_out_kernel(
    const float* __restrict__ feat,   // (M, 64)
    float* __restrict__ out,          // (B, 64, H, W)
    int n32)                          // out_size / 32
{
    int i = blockIdx.x * blockDim.x + threadIdx.x;
    if (i >= n32) return;

    int r8 = i % HW8;                 // cell-octet index within plane
    int t  = i / HW8;                 // b*16 + c4
    int c4 = t & 15;
    int b  = t >> 4;

    int cbase  = c4 * 4;
    int cell0  = b * HW + 8 * r8;

    // --- all loads first: 2 coalesced map reads, then 8 clamped feat reads
    const int4* mp = reinterpret_cast<const int4*>(&g_pillar_map[cell0]);
    int4 ma = mp[0];
    int4 mb = mp[1];

    int a0 = ma.x < 0 ? 0 : ma.x;
    int a1 = ma.y < 0 ? 0 : ma.y;
    int a2 = ma.z < 0 ? 0 : ma.z;
    int a3 = ma.w < 0 ? 0 : ma.w;
    int b0 = mb.x < 0 ? 0 : mb.x;
    int b1 = mb.y < 0 ? 0 : mb.y;
    int b2 = mb.z < 0 ? 0 : mb.z;
    int b3 = mb.w < 0 ? 0 : mb.w;

    float4 fa0 = __ldg(reinterpret_cast<const float4*>(&feat[a0 * C_CH + cbase]));
    float4 fa1 = __ldg(reinterpret_cast<const float4*>(&feat[a1 * C_CH + cbase]));
    float4 fa2 = __ldg(reinterpret_cast<const float4*>(&feat[a2 * C_CH + cbase]));
    float4 fa3 = __ldg(reinterpret_cast<const float4*>(&feat[a3 * C_CH + cbase]));
    float4 fb0 = __ldg(reinterpret_cast<const float4*>(&feat[b0 * C_CH + cbase]));
    float4 fb1 = __ldg(reinterpret_cast<const float4*>(&feat[b1 * C_CH + cbase]));
    float4 fb2 = __ldg(reinterpret_cast<const float4*>(&feat[b2 * C_CH + cbase]));
    float4 fb3 = __ldg(reinterpret_cast<const float4*>(&feat[b3 * C_CH + cbase]));

    // --- selects (branch-free)
    const float4 z4 = make_float4(0.f, 0.f, 0.f, 0.f);
    if (ma.x < 0) fa0 = z4;
    if (ma.y < 0) fa1 = z4;
    if (ma.z < 0) fa2 = z4;
    if (ma.w < 0) fa3 = z4;
    if (mb.x < 0) fb0 = z4;
    if (mb.y < 0) fb1 = z4;
    if (mb.z < 0) fb2 = z4;
    if (mb.w < 0) fb3 = z4;

    // --- 4x4 register transposes: per-channel vectors over cells
    long base = (long)(b * C_CH + cbase) * HW + 8 * r8;

    float4 o;
    o = make_float4(fa0.x, fa1.x, fa2.x, fa3.x);
    __stcs(reinterpret_cast<float4*>(&out[base + 0L * HW]), o);
    o = make_float4(fa0.y, fa1.y, fa2.y, fa3.y);
    __stcs(reinterpret_cast<float4*>(&out[base + 1L * HW]), o);
    o = make_float4(fa0.z, fa1.z, fa2.z, fa3.z);
    __stcs(reinterpret_cast<float4*>(&out[base + 2L * HW]), o);
    o = make_float4(fa0.w, fa1.w, fa2.w, fa3.w);
    __stcs(reinterpret_cast<float4*>(&out[base + 3L * HW]), o);

    o = make_float4(fb0.x, fb1.x, fb2.x, fb3.x);
    __stcs(reinterpret_cast<float4*>(&out[base + 4 + 0L * HW]), o);
    o = make_float4(fb0.y, fb1.y, fb2.y, fb3.y);
    __stcs(reinterpret_cast<float4*>(&out[base + 4 + 1L * HW]), o);
    o = make_float4(fb0.z, fb1.z, fb2.z, fb3.z);
    __stcs(reinterpret_cast<float4*>(&out[base + 4 + 2L * HW]), o);
    o = make_float4(fb0.w, fb1.w, fb2.w, fb3.w);
    __stcs(reinterpret_cast<float4*>(&out[base + 4 + 3L * HW]), o);
}

// ---------------------------------------------------------------------------
// Launch
// Inputs: [0] voxel_coords (M,3) int32, [1] voxel_features (M,64) f32,
//         [2] batch_size scalar (B derived from out_size instead).
// Output: (B, 64, 496, 432) float32
// ---------------------------------------------------------------------------
extern "C" void kernel_launch(void* const* d_in, const int* in_sizes, int n_in,
                              void* d_out, int out_size) {
    const int*   coords = (const int*)d_in[0];
    const float* feat   = (const float*)d_in[1];
    float*       out    = (float*)d_out;

    int M = in_sizes[0] / 3;
    int B = out_size / (C_CH * HW);
    if (B < 1) B = 1;
    if (B > MAXB) B = MAXB;

    // Clear the map with a memset node: 0xFF bytes == -1 per int.
    void* map_ptr = nullptr;
    cudaGetSymbolAddress(&map_ptr, g_pillar_map);
    cudaMemsetAsync(map_ptr, 0xFF, (size_t)B * HW * sizeof(int), 0);

    scatter_map_kernel<<<(M + 255) / 256, 256>>>(coords, M);

    int n32 = out_size / 32;             // 1,714,176 for B=4
    gather_out_kernel<<<(n32 + 255) / 256, 256>>>(feat, out, n32);
}

// round 15
// speedup vs baseline: 2.3631x; 2.3631x over previous
#include <cuda_runtime.h>
#include <cuda_bf16.h>
#include <stdint.h>

// PointPillars BEV scatter as a full-output gather.
//   out(B, C, H, W): out[b,c,y,x] = feat[map[b,y,x], c]  (or 0 if empty)
//
// R13 (resubmit): R6 gather (lane-consecutive quads, branch-free clamp+
// select) with ILP-2 via a FAR-STRIDE second quad (i + n16/2): per-quad
// coalescing byte-identical to R6, 10 independent loads per thread.
// Map cleared via cudaMemsetAsync node (0xFF == -1).

#define BEV_H 496
#define BEV_W 432
#define C_CH  64
#define HW    (BEV_H * BEV_W)     // 214,272
#define HW4   (HW / 4)            // 53,568
#define MAXB  8

__device__ int g_pillar_map[MAXB * HW];

// ---------------------------------------------------------------------------
// Kernel 1: scatter pillar indices (collision-free coords by construction)
// ---------------------------------------------------------------------------
__global__ void scatter_map_kernel(const int* __restrict__ coords, int M) {
    int m = blockIdx.x * blockDim.x + threadIdx.x;
    if (m < M) {
        int b = coords[3 * m + 0];
        int y = coords[3 * m + 1];
        int x = coords[3 * m + 2];
        g_pillar_map[b * HW + y * BEV_W + x] = m;
    }
}

// ---------------------------------------------------------------------------
// Quad address decomposition: quad q -> map offset, out base, channel base.
// ---------------------------------------------------------------------------
__device__ __forceinline__ void quad_addr(int q, int& map_off, long& obase,
                                          int& cbase) {
    int r  = q % HW4;                 // cell-quad index within plane
    int t  = q / HW4;                 // b*16 + c4
    int c4 = t & 15;
    int b  = t >> 4;
    cbase  = c4 * 4;
    map_off = b * HW + 4 * r;
    obase   = (long)(b * C_CH + cbase) * HW + 4 * r;
}

// ---------------------------------------------------------------------------
// Kernel 2: gather, ILP-2. Thread i handles quads i and i + half.
// Per quad: 1 coalesced map int4 + 4 clamped LDG.128 + 4x4 transpose +
// 4 coalesced STG.128 streaming stores. All 10 loads independent.
// ---------------------------------------------------------------------------
__global__ void __launch_bounds__(256) gather_out_kernel(
    const float* __restrict__ feat,   // (M, 64)
    float* __restrict__ out,          // (B, 64, H, W)
    int half)                         // n16 / 2
{
    int i = blockIdx.x * blockDim.x + threadIdx.x;
    if (i >= half) return;

    int  moff0, moff1, cb0, cb1;
    long ob0, ob1;
    quad_addr(i,        moff0, ob0, cb0);
    quad_addr(i + half, moff1, ob1, cb1);

    // --- all loads up front (independent): 2 map reads, 8 feat reads
    int4 ma = *reinterpret_cast<const int4*>(&g_pillar_map[moff0]);
    int4 mb = *reinterpret_cast<const int4*>(&g_pillar_map[moff1]);

    int a0 = ma.x < 0 ? 0 : ma.x;
    int a1 = ma.y < 0 ? 0 : ma.y;
    int a2 = ma.z < 0 ? 0 : ma.z;
    int a3 = ma.w < 0 ? 0 : ma.w;
    int b0 = mb.x < 0 ? 0 : mb.x;
    int b1 = mb.y < 0 ? 0 : mb.y;
    int b2 = mb.z < 0 ? 0 : mb.z;
    int b3 = mb.w < 0 ? 0 : mb.w;

    float4 fa0 = __ldg(reinterpret_cast<const float4*>(&feat[a0 * C_CH + cb0]));
    float4 fa1 = __ldg(reinterpret_cast<const float4*>(&feat[a1 * C_CH + cb0]));
    float4 fa2 = __ldg(reinterpret_cast<const float4*>(&feat[a2 * C_CH + cb0]));
    float4 fa3 = __ldg(reinterpret_cast<const float4*>(&feat[a3 * C_CH + cb0]));
    float4 fb0 = __ldg(reinterpret_cast<const float4*>(&feat[b0 * C_CH + cb1]));
    float4 fb1 = __ldg(reinterpret_cast<const float4*>(&feat[b1 * C_CH + cb1]));
    float4 fb2 = __ldg(reinterpret_cast<const float4*>(&feat[b2 * C_CH + cb1]));
    float4 fb3 = __ldg(reinterpret_cast<const float4*>(&feat[b3 * C_CH + cb1]));

    // --- branch-free selects
    const float4 z4 = make_float4(0.f, 0.f, 0.f, 0.f);
    if (ma.x < 0) fa0 = z4;
    if (ma.y < 0) fa1 = z4;
    if (ma.z < 0) fa2 = z4;
    if (ma.w < 0) fa3 = z4;
    if (mb.x < 0) fb0 = z4;
    if (mb.y < 0) fb1 = z4;
    if (mb.z < 0) fb2 = z4;
    if (mb.w < 0) fb3 = z4;

    // --- 4x4 register transposes + coalesced streaming stores
    float4 o;
    o = make_float4(fa0.x, fa1.x, fa2.x, fa3.x);
    __stcs(reinterpret_cast<float4*>(&out[ob0 + 0L * HW]), o);
    o = make_float4(fa0.y, fa1.y, fa2.y, fa3.y);
    __stcs(reinterpret_cast<float4*>(&out[ob0 + 1L * HW]), o);
    o = make_float4(fa0.z, fa1.z, fa2.z, fa3.z);
    __stcs(reinterpret_cast<float4*>(&out[ob0 + 2L * HW]), o);
    o = make_float4(fa0.w, fa1.w, fa2.w, fa3.w);
    __stcs(reinterpret_cast<float4*>(&out[ob0 + 3L * HW]), o);

    o = make_float4(fb0.x, fb1.x, fb2.x, fb3.x);
    __stcs(reinterpret_cast<float4*>(&out[ob1 + 0L * HW]), o);
    o = make_float4(fb0.y, fb1.y, fb2.y, fb3.y);
    __stcs(reinterpret_cast<float4*>(&out[ob1 + 1L * HW]), o);
    o = make_float4(fb0.z, fb1.z, fb2.z, fb3.z);
    __stcs(reinterpret_cast<float4*>(&out[ob1 + 2L * HW]), o);
    o = make_float4(fb0.w, fb1.w, fb2.w, fb3.w);
    __stcs(reinterpret_cast<float4*>(&out[ob1 + 3L * HW]), o);
}

// ---------------------------------------------------------------------------
// Launch
// Inputs: [0] voxel_coords (M,3) int32, [1] voxel_features (M,64) f32,
//         [2] batch_size scalar (B derived from out_size instead).
// Output: (B, 64, 496, 432) float32
// ---------------------------------------------------------------------------
extern "C" void kernel_launch(void* const* d_in, const int* in_sizes, int n_in,
                              void* d_out, int out_size) {
    const int*   coords = (const int*)d_in[0];
    const float* feat   = (const float*)d_in[1];
    float*       out    = (float*)d_out;

    int M = in_sizes[0] / 3;
    int B = out_size / (C_CH * HW);
    if (B < 1) B = 1;
    if (B > MAXB) B = MAXB;

    // Clear the map with a memset node: 0xFF bytes == -1 per int.
    void* map_ptr = nullptr;
    cudaGetSymbolAddress(&map_ptr, g_pillar_map);
    cudaMemsetAsync(map_ptr, 0xFF, (size_t)B * HW * sizeof(int), 0);

    scatter_map_kernel<<<(M + 255) / 256, 256>>>(coords, M);

    int half = (out_size / 16) / 2;      // 6,856,704 for B=4
    gather_out_kernel<<<(half + 255) / 256, 256>>>(feat, out, half);
}